// round 6
// baseline (speedup 1.0000x reference)
#include <cuda_runtime.h>
#include <math.h>
#include <stdint.h>

#define Bb   4
#define Nn   2048
#define FEAT 512
#define HIDD 512
#define Hh   8
#define HD   64
#define ROWS (Bb*Nn)          // 8192
#define BH   (Bb*Hh)          // 32

// ---------------- scratch (static device arrays; per-z doubled) ----------------
__device__ float g_qkv[(size_t)2*ROWS*3*HIDD];
__device__ float g_q[(size_t)2*ROWS*HIDD];    // [z][BH,N,HD], tf32 bits, q pre-scaled 1/8
__device__ float g_k[(size_t)2*ROWS*HIDD];
__device__ float g_v[(size_t)2*ROWS*HIDD];
__device__ float g_o[(size_t)2*ROWS*HIDD];    // [z][B,N,HID]
__device__ float g_msg[(size_t)2*ROWS*HIDD];
__device__ float g_h[(size_t)2*ROWS*2*FEAT];
__device__ float g_g[(size_t)2*ROWS*2*FEAT];

// ---------------- tf32 helpers ----------------
__device__ __forceinline__ uint32_t f2tf(float f) {
    uint32_t u;
    asm("cvt.rna.tf32.f32 %0, %1;" : "=r"(u) : "f"(f));
    return u;
}

__device__ __forceinline__ void mma_tf32(float* d,
    uint32_t a0, uint32_t a1, uint32_t a2, uint32_t a3,
    uint32_t b0, uint32_t b1)
{
    asm volatile(
        "mma.sync.aligned.m16n8k8.row.col.f32.tf32.tf32.f32 "
        "{%0,%1,%2,%3},{%4,%5,%6,%7},{%8,%9},{%0,%1,%2,%3};"
        : "+f"(d[0]), "+f"(d[1]), "+f"(d[2]), "+f"(d[3])
        : "r"(a0), "r"(a1), "r"(a2), "r"(a3), "r"(b0), "r"(b1));
}

// B pair-major layout for a 16(k) x 128(n) tile:
//  word(k,n) = (k>>3)*1096 + (k&3)*272 + 2*n + 2*(n>>4) + ((k>>2)&1)
// Fragment pair {B[c][n], B[c+4][n]} (c = ks*8+tig) is one aligned LDS.64.
#define GB_KS_PITCH 1096
#define GB_TIG_PITCH 272
#define GB_WORDS (2*GB_KS_PITCH)   // 2192 per stage

// ---------------- batched tf32 GEMM over z=0,1 ----------------
// 128x128 block tile, K-tile 16, 256 threads (8 warps, 4x2), warp tile 32x64.
__global__ __launch_bounds__(256, 2) void gemm_tf32(
    const float* __restrict__ A0, const float* __restrict__ A1, int lda,
    const float* __restrict__ A2_0, const float* __restrict__ A2_1, int lda2, int ksplit,
    const float* __restrict__ Bm, int ldb,
    const float* __restrict__ bias,
    const float* __restrict__ R0, const float* __restrict__ R1, int ldr,
    float* __restrict__ C, size_t zstrC, int ldc, int K)
{
    __shared__ uint32_t As[2][128*20];
    __shared__ uint32_t Bs[2][GB_WORDS];

    const int z = blockIdx.z;
    const float* A     = z ? A1   : A0;
    const float* A2    = z ? A2_1 : A2_0;
    const float* resid = z ? R1   : R0;
    float* Cz = C + (size_t)z * zstrC;

    const int t    = threadIdx.x;
    const int lane = t & 31;
    const int warp = t >> 5;
    const int wm   = warp & 3;
    const int wn   = warp >> 2;
    const int rb   = blockIdx.y * 128;
    const int cb   = blockIdx.x * 128;

    const int arow = t >> 1;
    const int ah   = (t & 1) * 8;
    const int bk   = t >> 4;           // 0..15 (k index within tile)
    const int bn   = (t & 15) * 4;     // 0..60

    const int ksb  = bk >> 3;
    const int tigb = bk & 3;
    const int phb  = (bk >> 2) & 1;
    const int bbase = ksb*GB_KS_PITCH + tigb*GB_TIG_PITCH + phb;
    const int w0 = bn*2 + (bn>>4)*2;
    const int w1 = (bn+64)*2 + ((bn+64)>>4)*2;

    const int gid  = lane >> 2;
    const int tig  = lane & 3;

    float acc[2][8][4] = {};

    float4 av0, av1, bv0, bv1;
    {
        int kg = ah;
        const float* asrc = (A2 && kg >= ksplit)
            ? A2 + (size_t)(rb + arow) * lda2 + (kg - ksplit)
            : A  + (size_t)(rb + arow) * lda  + kg;
        av0 = *(const float4*)asrc;
        av1 = *(const float4*)(asrc + 4);
        const float* bsrc = Bm + (size_t)bk * ldb + cb + bn;
        bv0 = *(const float4*)bsrc;
        bv1 = *(const float4*)(bsrc + 64);
    }
    {
        uint4 c0 = make_uint4(f2tf(av0.x), f2tf(av0.y), f2tf(av0.z), f2tf(av0.w));
        uint4 c1 = make_uint4(f2tf(av1.x), f2tf(av1.y), f2tf(av1.z), f2tf(av1.w));
        *(uint4*)&As[0][arow*20 + ah]     = c0;
        *(uint4*)&As[0][arow*20 + ah + 4] = c1;
        uint32_t* bp = &Bs[0][bbase];
        bp[w0+0]=f2tf(bv0.x); bp[w0+2]=f2tf(bv0.y); bp[w0+4]=f2tf(bv0.z); bp[w0+6]=f2tf(bv0.w);
        bp[w1+0]=f2tf(bv1.x); bp[w1+2]=f2tf(bv1.y); bp[w1+4]=f2tf(bv1.z); bp[w1+6]=f2tf(bv1.w);
    }
    __syncthreads();

    const int nk = K >> 4;
    for (int kt = 0; kt < nk; ++kt) {
        const int cur = kt & 1;
        if (kt + 1 < nk) {
            int kb = (kt + 1) << 4;
            int kg = kb + ah;
            const float* asrc = (A2 && kg >= ksplit)
                ? A2 + (size_t)(rb + arow) * lda2 + (kg - ksplit)
                : A  + (size_t)(rb + arow) * lda  + kg;
            av0 = *(const float4*)asrc;
            av1 = *(const float4*)(asrc + 4);
            const float* bsrc = Bm + (size_t)(kb + bk) * ldb + cb + bn;
            bv0 = *(const float4*)bsrc;
            bv1 = *(const float4*)(bsrc + 64);
        }

        const uint32_t* Ac = As[cur];
        const uint32_t* Bc = Bs[cur];
        #pragma unroll
        for (int ks = 0; ks < 2; ++ks) {
            uint32_t af[2][4];
            #pragma unroll
            for (int mt = 0; mt < 2; ++mt) {
                int r = wm*32 + mt*16 + gid;
                int c = ks*8 + tig;
                af[mt][0] = Ac[r*20 + c];
                af[mt][1] = Ac[(r+8)*20 + c];
                af[mt][2] = Ac[r*20 + c + 4];
                af[mt][3] = Ac[(r+8)*20 + c + 4];
            }
            const uint32_t* bbp = Bc + ks*GB_KS_PITCH + tig*GB_TIG_PITCH;
            #pragma unroll
            for (int nt = 0; nt < 8; ++nt) {
                int n = wn*64 + nt*8 + gid;
                uint2 bb = *(const uint2*)&bbp[n*2 + (wn*4 + (nt>>1))*2];
                mma_tf32(acc[0][nt], af[0][0], af[0][1], af[0][2], af[0][3], bb.x, bb.y);
                mma_tf32(acc[1][nt], af[1][0], af[1][1], af[1][2], af[1][3], bb.x, bb.y);
            }
        }

        if (kt + 1 < nk) {
            const int nxt = (kt + 1) & 1;
            uint4 c0 = make_uint4(f2tf(av0.x), f2tf(av0.y), f2tf(av0.z), f2tf(av0.w));
            uint4 c1 = make_uint4(f2tf(av1.x), f2tf(av1.y), f2tf(av1.z), f2tf(av1.w));
            *(uint4*)&As[nxt][arow*20 + ah]     = c0;
            *(uint4*)&As[nxt][arow*20 + ah + 4] = c1;
            uint32_t* bp = &Bs[nxt][bbase];
            bp[w0+0]=f2tf(bv0.x); bp[w0+2]=f2tf(bv0.y); bp[w0+4]=f2tf(bv0.z); bp[w0+6]=f2tf(bv0.w);
            bp[w1+0]=f2tf(bv1.x); bp[w1+2]=f2tf(bv1.y); bp[w1+4]=f2tf(bv1.z); bp[w1+6]=f2tf(bv1.w);
        }
        __syncthreads();
    }

    #pragma unroll
    for (int mt = 0; mt < 2; ++mt) {
        #pragma unroll
        for (int nt = 0; nt < 8; ++nt) {
            int row0 = rb + wm*32 + mt*16 + gid;
            int col  = cb + wn*64 + nt*8 + 2*tig;
            float2 bz = *(const float2*)(bias + col);
            float2 o0, o1;
            o0.x = acc[mt][nt][0] + bz.x;
            o0.y = acc[mt][nt][1] + bz.y;
            o1.x = acc[mt][nt][2] + bz.x;
            o1.y = acc[mt][nt][3] + bz.y;
            if (resid != nullptr) {
                float2 r0 = *(const float2*)(resid + (size_t)row0 * ldr + col);
                float2 r1 = *(const float2*)(resid + (size_t)(row0+8) * ldr + col);
                o0.x += r0.x; o0.y += r0.y;
                o1.x += r1.x; o1.y += r1.y;
            }
            *(float2*)(Cz + (size_t)row0 * ldc + col)     = o0;
            *(float2*)(Cz + (size_t)(row0+8) * ldc + col) = o1;
        }
    }
}

// ---------------- RoPE + split (batched over z); tf32-rounded; q pre-scaled 1/8 ----------------
__global__ __launch_bounds__(256) void rope_kernel(
    const float* __restrict__ qkv, const float* __restrict__ enc0,
    const float* __restrict__ enc1,
    float* __restrict__ qb, float* __restrict__ kb, float* __restrict__ vb)
{
    const int z = blockIdx.y;
    const float* enc = z ? enc1 : enc0;
    const float* qz  = qkv + (size_t)z * ROWS * 3*HIDD;
    const size_t zo  = (size_t)z * ROWS * HIDD;

    int idx = blockIdx.x * blockDim.x + threadIdx.x;
    int p  = idx & (HD/2 - 1);
    int tmp = idx >> 5;
    int h  = tmp & (Hh - 1);
    tmp >>= 3;
    int n  = tmp & (Nn - 1);
    int b  = tmp >> 11;

    size_t row  = (size_t)b * Nn + n;
    size_t base = row * (3*HIDD) + h * (HD*3) + (2*p)*3;
    float q0 = qz[base+0], k0 = qz[base+1], v0 = qz[base+2];
    float q1 = qz[base+3], k1 = qz[base+4], v1 = qz[base+5];

    size_t eb = row * HD + 2*p;
    const size_t ESTR = (size_t)Bb * Nn * HD;
    float f00 = enc[eb],      f01 = enc[eb+1];
    float f10 = enc[ESTR+eb], f11 = enc[ESTR+eb+1];

    float qo0 = (q0*f00 - q1*f10) * 0.125f;
    float qo1 = (q1*f01 + q0*f11) * 0.125f;
    float ko0 = k0*f00 - k1*f10;
    float ko1 = k1*f01 + k0*f11;

    size_t ob = zo + (((size_t)b*Hh + h) * Nn + n) * HD + 2*p;
    qb[ob]   = __uint_as_float(f2tf(qo0));
    qb[ob+1] = __uint_as_float(f2tf(qo1));
    kb[ob]   = __uint_as_float(f2tf(ko0));
    kb[ob+1] = __uint_as_float(f2tf(ko1));
    vb[ob]   = __uint_as_float(f2tf(v0));
    vb[ob+1] = __uint_as_float(f2tf(v1));
}

// ---------------- tf32 flash attention (batched over z) ----------------
// KV pair-major layout (64 contraction x 64 free):
//  word(c, n) = (c>>3)*552 + (c&3)*136 + 2*n + 2*(n>>4) + ((c>>2)&1)
#define FK_KS_PITCH 552
#define FK_TIG_PITCH 136
#define QOFF 0
#define KOFF (128*68)                 // 8704
#define VOFF (KOFF + 8*FK_KS_PITCH)   // +4416
#define POFF (VOFF + 8*FK_KS_PITCH)   // +4416
#define FLASH_SMEM_U32 (POFF + 128*68)

__global__ __launch_bounds__(256, 2) void flash_tf32(
    const float* __restrict__ Q, const float* __restrict__ K,
    const float* __restrict__ V, float* __restrict__ O)
{
    extern __shared__ uint32_t smu[];
    uint32_t* Qs = smu + QOFF;
    uint32_t* Ks = smu + KOFF;
    uint32_t* Vs = smu + VOFF;
    uint32_t* Ps = smu + POFF;

    const int z  = blockIdx.z;
    const int bh = blockIdx.y;
    const int b  = bh >> 3;
    const int h  = bh & 7;
    const size_t zo = (size_t)z * ROWS * HIDD;
    const uint32_t* Qg = (const uint32_t*)(Q + zo + (size_t)bh * Nn * HD);
    const uint32_t* Kg = (const uint32_t*)(K + zo + (size_t)bh * Nn * HD);
    const uint32_t* Vg = (const uint32_t*)(V + zo + (size_t)bh * Nn * HD);
    float* Og = O + zo;

    const int t    = threadIdx.x;
    const int lane = t & 31;
    const int warp = t >> 5;
    const int gid  = lane >> 2;
    const int tig  = lane & 3;
    const int q0r  = blockIdx.x * 128;

    // stage Q tile [row][68]
    #pragma unroll
    for (int i = 0; i < 8; ++i) {
        int idx = t + 256*i;
        int row = idx >> 4, dq = (idx & 15) << 2;
        *(uint4*)&Qs[row*68 + dq] = *(const uint4*)&Qg[(size_t)(q0r + row)*HD + dq];
    }
    __syncthreads();

    // hoist Q fragments for this warp's 16 rows (persist across kv loop)
    uint32_t qf[8][4];
    {
        int r = warp*16 + gid;
        #pragma unroll
        for (int ks = 0; ks < 8; ++ks) {
            int c = ks*8 + tig;
            qf[ks][0] = Qs[r*68 + c];
            qf[ks][1] = Qs[(r+8)*68 + c];
            qf[ks][2] = Qs[r*68 + c + 4];
            qf[ks][3] = Qs[(r+8)*68 + c + 4];
        }
    }

    float accO[8][4] = {};
    float mrow[2] = {-1e30f, -1e30f};
    float lrow[2] = {0.f, 0.f};

    for (int j0 = 0; j0 < Nn; j0 += 64) {
        __syncthreads();   // prior-iter PV reads of Ks/Vs complete
        // stage K (contraction=d) and V (contraction=kv) in pair-major layouts
        #pragma unroll
        for (int i = 0; i < 4; ++i) {
            int idx = t + 256*i;
            int row = idx >> 4;            // 0..63
            int dq  = (idx & 15) << 2;     // 0..60
            uint4 kv4 = *(const uint4*)&Kg[(size_t)(j0 + row)*HD + dq];
            int nbase = row*2 + (row>>4)*2;
            {
                int d = dq;
                Ks[(d>>3)*FK_KS_PITCH + (d&3)*FK_TIG_PITCH + nbase + ((d>>2)&1)] = kv4.x;
                d = dq+1;
                Ks[(d>>3)*FK_KS_PITCH + (d&3)*FK_TIG_PITCH + nbase + ((d>>2)&1)] = kv4.y;
                d = dq+2;
                Ks[(d>>3)*FK_KS_PITCH + (d&3)*FK_TIG_PITCH + nbase + ((d>>2)&1)] = kv4.z;
                d = dq+3;
                Ks[(d>>3)*FK_KS_PITCH + (d&3)*FK_TIG_PITCH + nbase + ((d>>2)&1)] = kv4.w;
            }
            uint4 vv4 = *(const uint4*)&Vg[(size_t)(j0 + row)*HD + dq];
            {
                uint32_t* vdst = &Vs[(row>>3)*FK_KS_PITCH + (row&3)*FK_TIG_PITCH + ((row>>2)&1)];
                int wv = dq*2 + (dq>>4)*2;
                vdst[wv+0] = vv4.x; vdst[wv+2] = vv4.y;
                vdst[wv+4] = vv4.z; vdst[wv+6] = vv4.w;
            }
        }
        __syncthreads();

        // S = Q @ K^T (q pre-scaled)
        float s[8][4] = {};
        #pragma unroll
        for (int ks = 0; ks < 8; ++ks) {
            const uint32_t* kbp = Ks + ks*FK_KS_PITCH + tig*FK_TIG_PITCH;
            #pragma unroll
            for (int nt = 0; nt < 8; ++nt) {
                int n = nt*8 + gid;
                uint2 bb = *(const uint2*)&kbp[n*2 + (nt>>1)*2];
                mma_tf32(s[nt], qf[ks][0], qf[ks][1], qf[ks][2], qf[ks][3], bb.x, bb.y);
            }
        }

        // online softmax per row-group
        #pragma unroll
        for (int g = 0; g < 2; ++g) {
            float tm = -1e30f;
            #pragma unroll
            for (int nt = 0; nt < 8; ++nt)
                tm = fmaxf(tm, fmaxf(s[nt][2*g], s[nt][2*g+1]));
            tm = fmaxf(tm, __shfl_xor_sync(0xffffffffu, tm, 1));
            tm = fmaxf(tm, __shfl_xor_sync(0xffffffffu, tm, 2));
            float mn = fmaxf(mrow[g], tm);
            float alpha = __expf(mrow[g] - mn);
            mrow[g] = mn;
            float rs = 0.f;
            #pragma unroll
            for (int nt = 0; nt < 8; ++nt) {
                float p0 = __expf(s[nt][2*g]   - mn);
                float p1 = __expf(s[nt][2*g+1] - mn);
                s[nt][2*g] = p0; s[nt][2*g+1] = p1;
                rs += p0 + p1;
            }
            rs += __shfl_xor_sync(0xffffffffu, rs, 1);
            rs += __shfl_xor_sync(0xffffffffu, rs, 2);
            lrow[g] = lrow[g]*alpha + rs;
            #pragma unroll
            for (int nt = 0; nt < 8; ++nt) {
                accO[nt][2*g]   *= alpha;
                accO[nt][2*g+1] *= alpha;
            }
        }

        // store P (tf32) to per-warp smem rows, vectorized pairs
        {
            int r0 = warp*16 + gid;
            #pragma unroll
            for (int nt = 0; nt < 8; ++nt) {
                int pc = nt*8 + 2*tig;
                uint2 p0 = make_uint2(f2tf(s[nt][0]), f2tf(s[nt][1]));
                uint2 p1 = make_uint2(f2tf(s[nt][2]), f2tf(s[nt][3]));
                *(uint2*)&Ps[r0*68 + pc]     = p0;
                *(uint2*)&Ps[(r0+8)*68 + pc] = p1;
            }
        }
        __syncwarp();

        // O += P @ V
        #pragma unroll
        for (int ks = 0; ks < 8; ++ks) {
            int r = warp*16 + gid;
            int c = ks*8 + tig;
            uint32_t a0 = Ps[r*68 + c];
            uint32_t a1 = Ps[(r+8)*68 + c];
            uint32_t a2 = Ps[r*68 + c + 4];
            uint32_t a3 = Ps[(r+8)*68 + c + 4];
            const uint32_t* vbp = Vs + ks*FK_KS_PITCH + tig*FK_TIG_PITCH;
            #pragma unroll
            for (int nt = 0; nt < 8; ++nt) {
                int n = nt*8 + gid;
                uint2 bb = *(const uint2*)&vbp[n*2 + (nt>>1)*2];
                mma_tf32(accO[nt], a0, a1, a2, a3, bb.x, bb.y);
            }
        }
    }

    #pragma unroll
    for (int g = 0; g < 2; ++g) {
        float inv = 1.0f / lrow[g];
        int n = q0r + warp*16 + gid + 8*g;
        #pragma unroll
        for (int nt = 0; nt < 8; ++nt) {
            int col = h*64 + nt*8 + 2*tig;
            float2 o;
            o.x = accO[nt][2*g]   * inv;
            o.y = accO[nt][2*g+1] * inv;
            *(float2*)&Og[((size_t)b * Nn + n) * HIDD + col] = o;
        }
    }
}

// ---------------- LayerNorm + exact GELU (batched over z) ----------------
__global__ __launch_bounds__(256) void ln_gelu_kernel(
    const float* __restrict__ H, const float* __restrict__ g,
    const float* __restrict__ bta, float* __restrict__ out)
{
    __shared__ float red[256];
    const size_t rowi = (size_t)blockIdx.y * ROWS + blockIdx.x;
    const float* p = H + rowi * (2*FEAT);
    int t = threadIdx.x;
    float4 v = ((const float4*)p)[t];

    float s = v.x + v.y + v.z + v.w;
    red[t] = s; __syncthreads();
    for (int ss = 128; ss > 0; ss >>= 1) {
        if (t < ss) red[t] += red[t+ss];
        __syncthreads();
    }
    float mu = red[0] * (1.0f / (2*FEAT));
    __syncthreads();

    float d0 = v.x - mu, d1 = v.y - mu, d2 = v.z - mu, d3 = v.w - mu;
    red[t] = d0*d0 + d1*d1 + d2*d2 + d3*d3; __syncthreads();
    for (int ss = 128; ss > 0; ss >>= 1) {
        if (t < ss) red[t] += red[t+ss];
        __syncthreads();
    }
    float var = red[0] * (1.0f / (2*FEAT));
    float rs = rsqrtf(var + 1e-5f);

    int c = t << 2;
    float4 gv = *(const float4*)(g + c);
    float4 bv = *(const float4*)(bta + c);
    float y0 = d0 * rs * gv.x + bv.x;
    float y1 = d1 * rs * gv.y + bv.y;
    float y2 = d2 * rs * gv.z + bv.z;
    float y3 = d3 * rs * gv.w + bv.w;

    const float IS2 = 0.70710678118654752f;
    float4 o;
    o.x = 0.5f * y0 * (1.0f + erff(y0 * IS2));
    o.y = 0.5f * y1 * (1.0f + erff(y1 * IS2));
    o.z = 0.5f * y2 * (1.0f + erff(y2 * IS2));
    o.w = 0.5f * y3 * (1.0f + erff(y3 * IS2));
    ((float4*)(out + rowi * (2*FEAT)))[t] = o;
}

extern "C" void kernel_launch(void* const* d_in, const int* in_sizes, int n_in,
                              void* d_out, int out_size)
{
    const float* x0    = (const float*)d_in[0];
    const float* x1    = (const float*)d_in[1];
    const float* enc0  = (const float*)d_in[2];
    const float* enc1  = (const float*)d_in[3];
    const float* Wqkv  = (const float*)d_in[4];
    const float* bqkv  = (const float*)d_in[5];
    const float* Wproj = (const float*)d_in[6];
    const float* bproj = (const float*)d_in[7];
    const float* W1    = (const float*)d_in[8];
    const float* b1    = (const float*)d_in[9];
    const float* ln_g  = (const float*)d_in[10];
    const float* ln_b  = (const float*)d_in[11];
    const float* W2    = (const float*)d_in[12];
    const float* b2    = (const float*)d_in[13];
    float* out = (float*)d_out;

    float *qkv, *q, *k, *v, *o, *msg, *hh, *gg;
    cudaGetSymbolAddress((void**)&qkv, g_qkv);
    cudaGetSymbolAddress((void**)&q,   g_q);
    cudaGetSymbolAddress((void**)&k,   g_k);
    cudaGetSymbolAddress((void**)&v,   g_v);
    cudaGetSymbolAddress((void**)&o,   g_o);
    cudaGetSymbolAddress((void**)&msg, g_msg);
    cudaGetSymbolAddress((void**)&hh,  g_h);
    cudaGetSymbolAddress((void**)&gg,  g_g);

    cudaFuncSetAttribute(flash_tf32,
        cudaFuncAttributeMaxDynamicSharedMemorySize, FLASH_SMEM_U32*4);

    const size_t ZQKV = (size_t)ROWS*3*HIDD;
    const size_t ZH   = (size_t)ROWS*HIDD;
    const size_t Z2F  = (size_t)ROWS*2*FEAT;

    // qkv = x @ Wqkv + bqkv
    gemm_tf32<<<dim3(3*HIDD/128, ROWS/128, 2), 256>>>(
        x0, x1, FEAT, nullptr, nullptr, 0, 1<<30,
        Wqkv, 3*HIDD, bqkv, nullptr, nullptr, 0,
        qkv, ZQKV, 3*HIDD, FEAT);

    rope_kernel<<<dim3((Bb*Nn*Hh*(HD/2))/256, 2), 256>>>(qkv, enc0, enc1, q, k, v);

    flash_tf32<<<dim3(Nn/128, BH, 2), 256, FLASH_SMEM_U32*4>>>(q, k, v, o);

    // message = O @ Wproj + bproj
    gemm_tf32<<<dim3(HIDD/128, ROWS/128, 2), 256>>>(
        o, o + ZH, HIDD, nullptr, nullptr, 0, 1<<30,
        Wproj, HIDD, bproj, nullptr, nullptr, 0,
        msg, ZH, HIDD, HIDD);

    // h = concat(x, msg) @ W1 + b1
    gemm_tf32<<<dim3(2*FEAT/128, ROWS/128, 2), 256>>>(
        x0, x1, FEAT, msg, msg + ZH, HIDD, FEAT,
        W1, 2*FEAT, b1, nullptr, nullptr, 0,
        hh, Z2F, 2*FEAT, FEAT + HIDD);

    ln_gelu_kernel<<<dim3(ROWS, 2), 256>>>(hh, ln_g, ln_b, gg);

    // out = x + g @ W2 + b2
    gemm_tf32<<<dim3(FEAT/128, ROWS/128, 2), 256>>>(
        gg, gg + Z2F, 2*FEAT, nullptr, nullptr, 0, 1<<30,
        W2, FEAT, b2, x0, x1, FEAT,
        out, (size_t)ROWS*FEAT, FEAT, 2*FEAT);
}

// round 7
// speedup vs baseline: 1.1282x; 1.1282x over previous
#include <cuda_runtime.h>
#include <math.h>
#include <stdint.h>

#define Bb   4
#define Nn   2048
#define FEAT 512
#define HIDD 512
#define Hh   8
#define HD   64
#define ROWS (Bb*Nn)          // 8192
#define BH   (Bb*Hh)          // 32

// ---------------- scratch (static device arrays; per-z doubled) ----------------
__device__ float g_qkv[(size_t)2*ROWS*3*HIDD];
__device__ float g_q[(size_t)2*ROWS*HIDD];    // [z][BH,N,HD], q pre-scaled 1/8
__device__ float g_k[(size_t)2*ROWS*HIDD];
__device__ float g_v[(size_t)2*ROWS*HIDD];
__device__ float g_o[(size_t)2*ROWS*HIDD];    // [z][B,N,HID]
__device__ float g_msg[(size_t)2*ROWS*HIDD];
__device__ float g_h[(size_t)2*ROWS*2*FEAT];
__device__ float g_g[(size_t)2*ROWS*2*FEAT];

// ---------------- helpers ----------------
__device__ __forceinline__ uint32_t s2u(const void* p) {
    return (uint32_t)__cvta_generic_to_shared(p);
}
__device__ __forceinline__ void cpa16(uint32_t dst, const void* src) {
    asm volatile("cp.async.cg.shared.global [%0], [%1], 16;\n" :: "r"(dst), "l"(src));
}
__device__ __forceinline__ void cpa_commit() {
    asm volatile("cp.async.commit_group;\n");
}
template<int N> __device__ __forceinline__ void cpa_wait() {
    asm volatile("cp.async.wait_group %0;\n" :: "n"(N));
}

// mma on raw fp32 bits: tensor core uses tf32 precision (low mantissa bits ignored)
__device__ __forceinline__ void mma_tf32(float* d,
    uint32_t a0, uint32_t a1, uint32_t a2, uint32_t a3,
    uint32_t b0, uint32_t b1)
{
    asm volatile(
        "mma.sync.aligned.m16n8k8.row.col.f32.tf32.tf32.f32 "
        "{%0,%1,%2,%3},{%4,%5,%6,%7},{%8,%9},{%0,%1,%2,%3};"
        : "+f"(d[0]), "+f"(d[1]), "+f"(d[2]), "+f"(d[3])
        : "r"(a0), "r"(a1), "r"(a2), "r"(a3), "r"(b0), "r"(b1));
}

// ---------------- batched tf32 GEMM over z=0,1; 3-stage cp.async pipeline ----------------
// 128x128 block tile, K-tile 16, 256 threads (8 warps, 4x2), warp tile 32x64.
// Per stage: A [128][20] (2560 w), B [16][136] (2176 w) -> 4736 words.
#define GST_WORDS 4736
#define GSM_BYTES (3*GST_WORDS*4)   // 56832

__global__ __launch_bounds__(256, 2) void gemm_tf32(
    const float* __restrict__ A0, const float* __restrict__ A1, int lda,
    const float* __restrict__ A2_0, const float* __restrict__ A2_1, int lda2, int ksplit,
    const float* __restrict__ Bm, int ldb,
    const float* __restrict__ bias,
    const float* __restrict__ R0, const float* __restrict__ R1, int ldr,
    float* __restrict__ C, size_t zstrC, int ldc, int K)
{
    extern __shared__ uint32_t gsm[];

    const int z = blockIdx.z;
    const float* A     = z ? A1   : A0;
    const float* A2    = z ? A2_1 : A2_0;
    const float* resid = z ? R1   : R0;
    float* Cz = C + (size_t)z * zstrC;

    const int t    = threadIdx.x;
    const int lane = t & 31;
    const int warp = t >> 5;
    const int wm   = warp & 3;
    const int wn   = warp >> 2;
    const int rb   = blockIdx.y * 128;
    const int cb   = blockIdx.x * 128;

    const int arow = t >> 1;          // 0..127
    const int ah   = (t & 1) * 8;     // 0 or 8
    const int bk   = t >> 4;          // 0..15
    const int bn8  = (t & 15) * 8;    // 0..120

    const int gid  = lane >> 2;
    const int tig  = lane & 3;

    const uint32_t smbase = s2u(gsm);

    // issue cp.async copies for K-tile kt into stage s
    auto issue_copy = [&](int kt, int s) {
        int kb = kt << 4;
        int kg = kb + ah;
        const float* asrc = (A2 && kg >= ksplit)
            ? A2 + (size_t)(rb + arow) * lda2 + (kg - ksplit)
            : A  + (size_t)(rb + arow) * lda  + kg;
        uint32_t adst = smbase + (uint32_t)(s*GST_WORDS + arow*20 + ah) * 4;
        cpa16(adst,      asrc);
        cpa16(adst + 16, asrc + 4);
        const float* bsrc = Bm + (size_t)(kb + bk) * ldb + cb + bn8;
        uint32_t bdst = smbase + (uint32_t)(s*GST_WORDS + 2560 + bk*136 + bn8) * 4;
        cpa16(bdst,      bsrc);
        cpa16(bdst + 16, bsrc + 4);
    };

    float acc[2][8][4] = {};

    const int nk = K >> 4;
    issue_copy(0, 0); cpa_commit();
    if (nk > 1) { issue_copy(1, 1); cpa_commit(); }

    for (int kt = 0; kt < nk; ++kt) {
        const int s = kt % 3;
        if (kt < nk - 1) cpa_wait<1>(); else cpa_wait<0>();
        __syncthreads();
        if (kt + 2 < nk) { issue_copy(kt + 2, (kt + 2) % 3); cpa_commit(); }

        const uint32_t* Ac = gsm + s*GST_WORDS;
        const uint32_t* Bc = gsm + s*GST_WORDS + 2560;
        #pragma unroll
        for (int ks = 0; ks < 2; ++ks) {
            uint32_t af[2][4];
            #pragma unroll
            for (int mt = 0; mt < 2; ++mt) {
                int r = wm*32 + mt*16 + gid;
                int c = ks*8 + tig;
                af[mt][0] = Ac[r*20 + c];
                af[mt][1] = Ac[(r+8)*20 + c];
                af[mt][2] = Ac[r*20 + c + 4];
                af[mt][3] = Ac[(r+8)*20 + c + 4];
            }
            #pragma unroll
            for (int nt = 0; nt < 8; ++nt) {
                int n = wn*64 + nt*8 + gid;
                int k = ks*8 + tig;
                uint32_t b0 = Bc[k*136 + n];
                uint32_t b1 = Bc[(k+4)*136 + n];
                mma_tf32(acc[0][nt], af[0][0], af[0][1], af[0][2], af[0][3], b0, b1);
                mma_tf32(acc[1][nt], af[1][0], af[1][1], af[1][2], af[1][3], b0, b1);
            }
        }
    }

    #pragma unroll
    for (int mt = 0; mt < 2; ++mt) {
        #pragma unroll
        for (int nt = 0; nt < 8; ++nt) {
            int row0 = rb + wm*32 + mt*16 + gid;
            int col  = cb + wn*64 + nt*8 + 2*tig;
            float2 bz = *(const float2*)(bias + col);
            float2 o0, o1;
            o0.x = acc[mt][nt][0] + bz.x;
            o0.y = acc[mt][nt][1] + bz.y;
            o1.x = acc[mt][nt][2] + bz.x;
            o1.y = acc[mt][nt][3] + bz.y;
            if (resid != nullptr) {
                float2 r0 = *(const float2*)(resid + (size_t)row0 * ldr + col);
                float2 r1 = *(const float2*)(resid + (size_t)(row0+8) * ldr + col);
                o0.x += r0.x; o0.y += r0.y;
                o1.x += r1.x; o1.y += r1.y;
            }
            *(float2*)(Cz + (size_t)row0 * ldc + col)     = o0;
            *(float2*)(Cz + (size_t)(row0+8) * ldc + col) = o1;
        }
    }
}

// ---------------- RoPE + split (batched over z); q pre-scaled 1/8 ----------------
__global__ __launch_bounds__(256) void rope_kernel(
    const float* __restrict__ qkv, const float* __restrict__ enc0,
    const float* __restrict__ enc1,
    float* __restrict__ qb, float* __restrict__ kb, float* __restrict__ vb)
{
    const int z = blockIdx.y;
    const float* enc = z ? enc1 : enc0;
    const float* qz  = qkv + (size_t)z * ROWS * 3*HIDD;
    const size_t zo  = (size_t)z * ROWS * HIDD;

    int idx = blockIdx.x * blockDim.x + threadIdx.x;
    int p  = idx & (HD/2 - 1);
    int tmp = idx >> 5;
    int h  = tmp & (Hh - 1);
    tmp >>= 3;
    int n  = tmp & (Nn - 1);
    int b  = tmp >> 11;

    size_t row  = (size_t)b * Nn + n;
    size_t base = row * (3*HIDD) + h * (HD*3) + (2*p)*3;
    float q0 = qz[base+0], k0 = qz[base+1], v0 = qz[base+2];
    float q1 = qz[base+3], k1 = qz[base+4], v1 = qz[base+5];

    size_t eb = row * HD + 2*p;
    const size_t ESTR = (size_t)Bb * Nn * HD;
    float f00 = enc[eb],      f01 = enc[eb+1];
    float f10 = enc[ESTR+eb], f11 = enc[ESTR+eb+1];

    float qo0 = (q0*f00 - q1*f10) * 0.125f;
    float qo1 = (q1*f01 + q0*f11) * 0.125f;
    float ko0 = k0*f00 - k1*f10;
    float ko1 = k1*f01 + k0*f11;

    size_t ob = zo + (((size_t)b*Hh + h) * Nn + n) * HD + 2*p;
    qb[ob]   = qo0; qb[ob+1] = qo1;
    kb[ob]   = ko0; kb[ob+1] = ko1;
    vb[ob]   = v0;  vb[ob+1] = v1;
}

// ---------------- tf32 flash attention (batched over z), R4 layout + cp.async ----------------
// smem words: Q[128][68], K[64][68], V[64][72], P[128][68]
#define QOFF 0
#define KOFF (128*68)
#define VOFF (KOFF + 64*68)
#define POFF (VOFF + 64*72)
#define FLASH_SMEM_U32 (POFF + 128*68)

__global__ __launch_bounds__(256, 2) void flash_tf32(
    const float* __restrict__ Q, const float* __restrict__ K,
    const float* __restrict__ V, float* __restrict__ O)
{
    extern __shared__ uint32_t smu[];
    uint32_t* Qs = smu + QOFF;
    uint32_t* Ks = smu + KOFF;
    uint32_t* Vs = smu + VOFF;
    float*    Ps = (float*)(smu + POFF);

    const int z  = blockIdx.z;
    const int bh = blockIdx.y;
    const int b  = bh >> 3;
    const int h  = bh & 7;
    const size_t zo = (size_t)z * ROWS * HIDD;
    const float* Qg = Q + zo + (size_t)bh * Nn * HD;
    const float* Kg = K + zo + (size_t)bh * Nn * HD;
    const float* Vg = V + zo + (size_t)bh * Nn * HD;
    float* Og = O + zo;

    const int t    = threadIdx.x;
    const int lane = t & 31;
    const int warp = t >> 5;
    const int gid  = lane >> 2;
    const int tig  = lane & 3;
    const int q0r  = blockIdx.x * 128;

    const uint32_t qsa = s2u(Qs);
    const uint32_t ksa = s2u(Ks);
    const uint32_t vsa = s2u(Vs);

    // stage Q tile [row][68] via cp.async
    #pragma unroll
    for (int i = 0; i < 8; ++i) {
        int idx = t + 256*i;
        int row = idx >> 4, dq = (idx & 15) << 2;
        cpa16(qsa + (uint32_t)(row*68 + dq)*4, Qg + (size_t)(q0r + row)*HD + dq);
    }
    cpa_commit();

    float accO[8][4] = {};
    float mrow[2] = {-1e30f, -1e30f};
    float lrow[2] = {0.f, 0.f};

    for (int j0 = 0; j0 < Nn; j0 += 64) {
        __syncthreads();   // prior-iter reads of Ks/Vs/Ps complete
        // stage K [kv][68] and V [kv][72] via cp.async
        #pragma unroll
        for (int i = 0; i < 4; ++i) {
            int idx = t + 256*i;
            int row = idx >> 4, dq = (idx & 15) << 2;
            cpa16(ksa + (uint32_t)(row*68 + dq)*4, Kg + (size_t)(j0 + row)*HD + dq);
            cpa16(vsa + (uint32_t)(row*72 + dq)*4, Vg + (size_t)(j0 + row)*HD + dq);
        }
        cpa_commit();
        cpa_wait<0>();
        __syncthreads();

        // S = Q @ K^T (q pre-scaled)
        float s[8][4] = {};
        #pragma unroll
        for (int ks = 0; ks < 8; ++ks) {
            int r = warp*16 + gid;
            int c = ks*8 + tig;
            uint32_t a0 = Qs[r*68 + c];
            uint32_t a1 = Qs[(r+8)*68 + c];
            uint32_t a2 = Qs[r*68 + c + 4];
            uint32_t a3 = Qs[(r+8)*68 + c + 4];
            #pragma unroll
            for (int nt = 0; nt < 8; ++nt) {
                int n = nt*8 + gid;
                int k = ks*8 + tig;
                uint32_t b0 = Ks[n*68 + k];
                uint32_t b1 = Ks[n*68 + k + 4];
                mma_tf32(s[nt], a0, a1, a2, a3, b0, b1);
            }
        }

        // online softmax per row-group
        #pragma unroll
        for (int g = 0; g < 2; ++g) {
            float tm = -1e30f;
            #pragma unroll
            for (int nt = 0; nt < 8; ++nt)
                tm = fmaxf(tm, fmaxf(s[nt][2*g], s[nt][2*g+1]));
            tm = fmaxf(tm, __shfl_xor_sync(0xffffffffu, tm, 1));
            tm = fmaxf(tm, __shfl_xor_sync(0xffffffffu, tm, 2));
            float mn = fmaxf(mrow[g], tm);
            float alpha = __expf(mrow[g] - mn);
            mrow[g] = mn;
            float rs = 0.f;
            #pragma unroll
            for (int nt = 0; nt < 8; ++nt) {
                float p0 = __expf(s[nt][2*g]   - mn);
                float p1 = __expf(s[nt][2*g+1] - mn);
                s[nt][2*g] = p0; s[nt][2*g+1] = p1;
                rs += p0 + p1;
            }
            rs += __shfl_xor_sync(0xffffffffu, rs, 1);
            rs += __shfl_xor_sync(0xffffffffu, rs, 2);
            lrow[g] = lrow[g]*alpha + rs;
            #pragma unroll
            for (int nt = 0; nt < 8; ++nt) {
                accO[nt][2*g]   *= alpha;
                accO[nt][2*g+1] *= alpha;
            }
        }

        // store P (raw fp32; tensor core truncates to tf32) to per-warp smem rows
        {
            int r0 = warp*16 + gid;
            #pragma unroll
            for (int nt = 0; nt < 8; ++nt) {
                int pc = nt*8 + 2*tig;
                *(float2*)&Ps[r0*68 + pc]     = make_float2(s[nt][0], s[nt][1]);
                *(float2*)&Ps[(r0+8)*68 + pc] = make_float2(s[nt][2], s[nt][3]);
            }
        }
        __syncwarp();

        // O += P @ V
        #pragma unroll
        for (int ks = 0; ks < 8; ++ks) {
            int r = warp*16 + gid;
            int c = ks*8 + tig;
            uint32_t a0 = ((uint32_t*)Ps)[r*68 + c];
            uint32_t a1 = ((uint32_t*)Ps)[(r+8)*68 + c];
            uint32_t a2 = ((uint32_t*)Ps)[r*68 + c + 4];
            uint32_t a3 = ((uint32_t*)Ps)[(r+8)*68 + c + 4];
            #pragma unroll
            for (int nt = 0; nt < 8; ++nt) {
                int n = nt*8 + gid;
                int k = ks*8 + tig;
                uint32_t b0 = Vs[k*72 + n];
                uint32_t b1 = Vs[(k+4)*72 + n];
                mma_tf32(accO[nt], a0, a1, a2, a3, b0, b1);
            }
        }
    }

    #pragma unroll
    for (int g = 0; g < 2; ++g) {
        float inv = 1.0f / lrow[g];
        int n = q0r + warp*16 + gid + 8*g;
        #pragma unroll
        for (int nt = 0; nt < 8; ++nt) {
            int col = h*64 + nt*8 + 2*tig;
            float2 o;
            o.x = accO[nt][2*g]   * inv;
            o.y = accO[nt][2*g+1] * inv;
            *(float2*)&Og[((size_t)b * Nn + n) * HIDD + col] = o;
        }
    }
}

// ---------------- LayerNorm + exact GELU (batched over z) ----------------
__global__ __launch_bounds__(256) void ln_gelu_kernel(
    const float* __restrict__ H, const float* __restrict__ g,
    const float* __restrict__ bta, float* __restrict__ out)
{
    __shared__ float red[256];
    const size_t rowi = (size_t)blockIdx.y * ROWS + blockIdx.x;
    const float* p = H + rowi * (2*FEAT);
    int t = threadIdx.x;
    float4 v = ((const float4*)p)[t];

    float s = v.x + v.y + v.z + v.w;
    red[t] = s; __syncthreads();
    for (int ss = 128; ss > 0; ss >>= 1) {
        if (t < ss) red[t] += red[t+ss];
        __syncthreads();
    }
    float mu = red[0] * (1.0f / (2*FEAT));
    __syncthreads();

    float d0 = v.x - mu, d1 = v.y - mu, d2 = v.z - mu, d3 = v.w - mu;
    red[t] = d0*d0 + d1*d1 + d2*d2 + d3*d3; __syncthreads();
    for (int ss = 128; ss > 0; ss >>= 1) {
        if (t < ss) red[t] += red[t+ss];
        __syncthreads();
    }
    float var = red[0] * (1.0f / (2*FEAT));
    float rs = rsqrtf(var + 1e-5f);

    int c = t << 2;
    float4 gv = *(const float4*)(g + c);
    float4 bv = *(const float4*)(bta + c);
    float y0 = d0 * rs * gv.x + bv.x;
    float y1 = d1 * rs * gv.y + bv.y;
    float y2 = d2 * rs * gv.z + bv.z;
    float y3 = d3 * rs * gv.w + bv.w;

    const float IS2 = 0.70710678118654752f;
    float4 o;
    o.x = 0.5f * y0 * (1.0f + erff(y0 * IS2));
    o.y = 0.5f * y1 * (1.0f + erff(y1 * IS2));
    o.z = 0.5f * y2 * (1.0f + erff(y2 * IS2));
    o.w = 0.5f * y3 * (1.0f + erff(y3 * IS2));
    ((float4*)(out + rowi * (2*FEAT)))[t] = o;
}

extern "C" void kernel_launch(void* const* d_in, const int* in_sizes, int n_in,
                              void* d_out, int out_size)
{
    const float* x0    = (const float*)d_in[0];
    const float* x1    = (const float*)d_in[1];
    const float* enc0  = (const float*)d_in[2];
    const float* enc1  = (const float*)d_in[3];
    const float* Wqkv  = (const float*)d_in[4];
    const float* bqkv  = (const float*)d_in[5];
    const float* Wproj = (const float*)d_in[6];
    const float* bproj = (const float*)d_in[7];
    const float* W1    = (const float*)d_in[8];
    const float* b1    = (const float*)d_in[9];
    const float* ln_g  = (const float*)d_in[10];
    const float* ln_b  = (const float*)d_in[11];
    const float* W2    = (const float*)d_in[12];
    const float* b2    = (const float*)d_in[13];
    float* out = (float*)d_out;

    float *qkv, *q, *k, *v, *o, *msg, *hh, *gg;
    cudaGetSymbolAddress((void**)&qkv, g_qkv);
    cudaGetSymbolAddress((void**)&q,   g_q);
    cudaGetSymbolAddress((void**)&k,   g_k);
    cudaGetSymbolAddress((void**)&v,   g_v);
    cudaGetSymbolAddress((void**)&o,   g_o);
    cudaGetSymbolAddress((void**)&msg, g_msg);
    cudaGetSymbolAddress((void**)&hh,  g_h);
    cudaGetSymbolAddress((void**)&gg,  g_g);

    cudaFuncSetAttribute(gemm_tf32,
        cudaFuncAttributeMaxDynamicSharedMemorySize, GSM_BYTES);
    cudaFuncSetAttribute(flash_tf32,
        cudaFuncAttributeMaxDynamicSharedMemorySize, FLASH_SMEM_U32*4);

    const size_t ZQKV = (size_t)ROWS*3*HIDD;
    const size_t ZH   = (size_t)ROWS*HIDD;
    const size_t Z2F  = (size_t)ROWS*2*FEAT;

    // qkv = x @ Wqkv + bqkv
    gemm_tf32<<<dim3(3*HIDD/128, ROWS/128, 2), 256, GSM_BYTES>>>(
        x0, x1, FEAT, nullptr, nullptr, 0, 1<<30,
        Wqkv, 3*HIDD, bqkv, nullptr, nullptr, 0,
        qkv, ZQKV, 3*HIDD, FEAT);

    rope_kernel<<<dim3((Bb*Nn*Hh*(HD/2))/256, 2), 256>>>(qkv, enc0, enc1, q, k, v);

    flash_tf32<<<dim3(Nn/128, BH, 2), 256, FLASH_SMEM_U32*4>>>(q, k, v, o);

    // message = O @ Wproj + bproj
    gemm_tf32<<<dim3(HIDD/128, ROWS/128, 2), 256, GSM_BYTES>>>(
        o, o + ZH, HIDD, nullptr, nullptr, 0, 1<<30,
        Wproj, HIDD, bproj, nullptr, nullptr, 0,
        msg, ZH, HIDD, HIDD);

    // h = concat(x, msg) @ W1 + b1
    gemm_tf32<<<dim3(2*FEAT/128, ROWS/128, 2), 256, GSM_BYTES>>>(
        x0, x1, FEAT, msg, msg + ZH, HIDD, FEAT,
        W1, 2*FEAT, b1, nullptr, nullptr, 0,
        hh, Z2F, 2*FEAT, FEAT + HIDD);

    ln_gelu_kernel<<<dim3(ROWS, 2), 256>>>(hh, ln_g, ln_b, gg);

    // out = x + g @ W2 + b2
    gemm_tf32<<<dim3(FEAT/128, ROWS/128, 2), 256, GSM_BYTES>>>(
        gg, gg + Z2F, 2*FEAT, nullptr, nullptr, 0, 1<<30,
        W2, FEAT, b2, x0, x1, FEAT,
        out, (size_t)ROWS*FEAT, FEAT, 2*FEAT);
}

// round 8
// speedup vs baseline: 1.1873x; 1.0524x over previous
#include <cuda_runtime.h>
#include <math.h>
#include <stdint.h>

#define Bb   4
#define Nn   2048
#define FEAT 512
#define HIDD 512
#define Hh   8
#define HD   64
#define ROWS (Bb*Nn)          // 8192
#define BH   (Bb*Hh)          // 32

// ---------------- scratch (static device arrays; per-z doubled) ----------------
__device__ float g_qkv[(size_t)2*ROWS*3*HIDD];
__device__ float g_q[(size_t)2*ROWS*HIDD];    // [z][BH,N,HD], q pre-scaled 1/8
__device__ float g_k[(size_t)2*ROWS*HIDD];
__device__ float g_v[(size_t)2*ROWS*HIDD];
__device__ float g_o[(size_t)2*ROWS*HIDD];    // [z][B,N,HID]
__device__ float g_msg[(size_t)2*ROWS*HIDD];
__device__ float g_h[(size_t)2*ROWS*2*FEAT];
__device__ float g_g[(size_t)2*ROWS*2*FEAT];
// transposed weights [N][K]
__device__ float g_wqkvT[(size_t)(3*HIDD)*FEAT];
__device__ float g_wprojT[(size_t)HIDD*HIDD];
__device__ float g_w1T[(size_t)(2*FEAT)*(FEAT+HIDD)];
__device__ float g_w2T[(size_t)FEAT*(2*FEAT)];

// ---------------- helpers ----------------
__device__ __forceinline__ uint32_t s2u(const void* p) {
    return (uint32_t)__cvta_generic_to_shared(p);
}
__device__ __forceinline__ void cpa16(uint32_t dst, const void* src) {
    asm volatile("cp.async.cg.shared.global [%0], [%1], 16;\n" :: "r"(dst), "l"(src));
}
__device__ __forceinline__ void cpa_commit() {
    asm volatile("cp.async.commit_group;\n");
}
template<int N> __device__ __forceinline__ void cpa_wait() {
    asm volatile("cp.async.wait_group %0;\n" :: "n"(N));
}
__device__ __forceinline__ void ldsm_x4(uint32_t& r0, uint32_t& r1,
                                        uint32_t& r2, uint32_t& r3, uint32_t addr) {
    asm volatile("ldmatrix.sync.aligned.m8n8.x4.shared.b16 {%0,%1,%2,%3}, [%4];"
        : "=r"(r0), "=r"(r1), "=r"(r2), "=r"(r3) : "r"(addr));
}

// mma on raw fp32 bits: tensor core truncates to tf32
__device__ __forceinline__ void mma_tf32(float* d,
    uint32_t a0, uint32_t a1, uint32_t a2, uint32_t a3,
    uint32_t b0, uint32_t b1)
{
    asm volatile(
        "mma.sync.aligned.m16n8k8.row.col.f32.tf32.tf32.f32 "
        "{%0,%1,%2,%3},{%4,%5,%6,%7},{%8,%9},{%0,%1,%2,%3};"
        : "+f"(d[0]), "+f"(d[1]), "+f"(d[2]), "+f"(d[3])
        : "r"(a0), "r"(a1), "r"(a2), "r"(a3), "r"(b0), "r"(b1));
}

// ---------------- 32x32 transpose: dst[C][R] = src[R][C]^T ----------------
__global__ __launch_bounds__(256) void tr_kernel(
    const float* __restrict__ src, float* __restrict__ dst, int R, int C)
{
    __shared__ float tile[32][33];
    int tx = threadIdx.x & 31, ty = threadIdx.x >> 5;   // 32 x 8
    int x = blockIdx.x*32 + tx;
    #pragma unroll
    for (int i = ty; i < 32; i += 8) {
        int y = blockIdx.y*32 + i;
        tile[i][tx] = src[(size_t)y*C + x];
    }
    __syncthreads();
    int xt = blockIdx.y*32 + tx;
    #pragma unroll
    for (int i = ty; i < 32; i += 8) {
        int yt = blockIdx.x*32 + i;
        dst[(size_t)yt*R + xt] = tile[tx][i];
    }
}

// ---------------- batched tf32 GEMM over z=0,1; 3-stage cp.async + LDSM ----------------
// 128x128 block tile, K-tile 16, 256 threads (8 warps, 4x2), warp tile 32x64.
// Stage: A [128][20] (2560 w) + B^T [128][20] (2560 w) = 5120 words.
#define GST_WORDS 5120
#define GSM_BYTES (3*GST_WORDS*4)   // 61440

__global__ __launch_bounds__(256, 2) void gemm_tf32(
    const float* __restrict__ A0, const float* __restrict__ A1, int lda,
    const float* __restrict__ A2_0, const float* __restrict__ A2_1, int lda2, int ksplit,
    const float* __restrict__ BT,
    const float* __restrict__ bias,
    const float* __restrict__ R0, const float* __restrict__ R1, int ldr,
    float* __restrict__ C, size_t zstrC, int ldc, int K)
{
    extern __shared__ uint32_t gsm[];

    const int z = blockIdx.z;
    const float* A     = z ? A1   : A0;
    const float* A2    = z ? A2_1 : A2_0;
    const float* resid = z ? R1   : R0;
    float* Cz = C + (size_t)z * zstrC;

    const int t    = threadIdx.x;
    const int lane = t & 31;
    const int warp = t >> 5;
    const int wm   = warp & 3;
    const int wn   = warp >> 2;
    const int rb   = blockIdx.y * 128;
    const int cb   = blockIdx.x * 128;

    const int arow = t >> 1;          // 0..127
    const int ah   = (t & 1) * 8;     // 0 or 8

    const int gid  = lane >> 2;
    const int tig  = lane & 3;

    // ldsm address components
    const int a_r = ((lane >> 3) & 1)*8 + (lane & 7);   // row within 16-row group
    const int a_c = (lane >> 4) * 4;                    // col-quad select
    const int b_r = (lane >> 4)*8 + (lane & 7);         // row within 16-row (2 n-tiles)
    const int b_c = ((lane >> 3) & 1) * 4;

    const uint32_t smbase = s2u(gsm);

    auto issue_copy = [&](int kt, int s) {
        int kg = (kt << 4) + ah;
        const float* asrc = (A2 && kg >= ksplit)
            ? A2 + (size_t)(rb + arow) * lda2 + (kg - ksplit)
            : A  + (size_t)(rb + arow) * lda  + kg;
        uint32_t adst = smbase + (uint32_t)(s*GST_WORDS + arow*20 + ah) * 4;
        cpa16(adst,      asrc);
        cpa16(adst + 16, asrc + 4);
        const float* bsrc = BT + (size_t)(cb + arow) * K + kg;
        uint32_t bdst = smbase + (uint32_t)(s*GST_WORDS + 2560 + arow*20 + ah) * 4;
        cpa16(bdst,      bsrc);
        cpa16(bdst + 16, bsrc + 4);
    };

    float acc[2][8][4] = {};

    const int nk = K >> 4;
    issue_copy(0, 0); cpa_commit();
    if (nk > 1) { issue_copy(1, 1); cpa_commit(); }

    for (int kt = 0; kt < nk; ++kt) {
        const int s = kt % 3;
        if (kt < nk - 1) cpa_wait<1>(); else cpa_wait<0>();
        __syncthreads();
        if (kt + 2 < nk) { issue_copy(kt + 2, (kt + 2) % 3); cpa_commit(); }

        const uint32_t abase = smbase + (uint32_t)(s*GST_WORDS)*4;
        const uint32_t bbase = abase + 2560*4;
        #pragma unroll
        for (int ks = 0; ks < 2; ++ks) {
            uint32_t af0[4], af1[4];
            ldsm_x4(af0[0], af0[1], af0[2], af0[3],
                abase + (uint32_t)((wm*32 + a_r)*20 + ks*8 + a_c)*4);
            ldsm_x4(af1[0], af1[1], af1[2], af1[3],
                abase + (uint32_t)((wm*32 + 16 + a_r)*20 + ks*8 + a_c)*4);
            #pragma unroll
            for (int j = 0; j < 4; ++j) {
                uint32_t bf0, bf1, bf2, bf3;
                ldsm_x4(bf0, bf1, bf2, bf3,
                    bbase + (uint32_t)((wn*64 + j*16 + b_r)*20 + ks*8 + b_c)*4);
                mma_tf32(acc[0][2*j],   af0[0], af0[1], af0[2], af0[3], bf0, bf1);
                mma_tf32(acc[1][2*j],   af1[0], af1[1], af1[2], af1[3], bf0, bf1);
                mma_tf32(acc[0][2*j+1], af0[0], af0[1], af0[2], af0[3], bf2, bf3);
                mma_tf32(acc[1][2*j+1], af1[0], af1[1], af1[2], af1[3], bf2, bf3);
            }
        }
    }

    #pragma unroll
    for (int mt = 0; mt < 2; ++mt) {
        #pragma unroll
        for (int nt = 0; nt < 8; ++nt) {
            int row0 = rb + wm*32 + mt*16 + gid;
            int col  = cb + wn*64 + nt*8 + 2*tig;
            float2 bz = *(const float2*)(bias + col);
            float2 o0, o1;
            o0.x = acc[mt][nt][0] + bz.x;
            o0.y = acc[mt][nt][1] + bz.y;
            o1.x = acc[mt][nt][2] + bz.x;
            o1.y = acc[mt][nt][3] + bz.y;
            if (resid != nullptr) {
                float2 r0 = *(const float2*)(resid + (size_t)row0 * ldr + col);
                float2 r1 = *(const float2*)(resid + (size_t)(row0+8) * ldr + col);
                o0.x += r0.x; o0.y += r0.y;
                o1.x += r1.x; o1.y += r1.y;
            }
            *(float2*)(Cz + (size_t)row0 * ldc + col)     = o0;
            *(float2*)(Cz + (size_t)(row0+8) * ldc + col) = o1;
        }
    }
}

// ---------------- RoPE + split (batched over z); q pre-scaled 1/8 ----------------
__global__ __launch_bounds__(256) void rope_kernel(
    const float* __restrict__ qkv, const float* __restrict__ enc0,
    const float* __restrict__ enc1,
    float* __restrict__ qb, float* __restrict__ kb, float* __restrict__ vb)
{
    const int z = blockIdx.y;
    const float* enc = z ? enc1 : enc0;
    const float* qz  = qkv + (size_t)z * ROWS * 3*HIDD;
    const size_t zo  = (size_t)z * ROWS * HIDD;

    int idx = blockIdx.x * blockDim.x + threadIdx.x;
    int p  = idx & (HD/2 - 1);
    int tmp = idx >> 5;
    int h  = tmp & (Hh - 1);
    tmp >>= 3;
    int n  = tmp & (Nn - 1);
    int b  = tmp >> 11;

    size_t row  = (size_t)b * Nn + n;
    size_t base = row * (3*HIDD) + h * (HD*3) + (2*p)*3;
    float q0 = qz[base+0], k0 = qz[base+1], v0 = qz[base+2];
    float q1 = qz[base+3], k1 = qz[base+4], v1 = qz[base+5];

    size_t eb = row * HD + 2*p;
    const size_t ESTR = (size_t)Bb * Nn * HD;
    float f00 = enc[eb],      f01 = enc[eb+1];
    float f10 = enc[ESTR+eb], f11 = enc[ESTR+eb+1];

    float qo0 = (q0*f00 - q1*f10) * 0.125f;
    float qo1 = (q1*f01 + q0*f11) * 0.125f;
    float ko0 = k0*f00 - k1*f10;
    float ko1 = k1*f01 + k0*f11;

    size_t ob = zo + (((size_t)b*Hh + h) * Nn + n) * HD + 2*p;
    qb[ob]   = qo0; qb[ob+1] = qo1;
    kb[ob]   = ko0; kb[ob+1] = ko1;
    vb[ob]   = v0;  vb[ob+1] = v1;
}

// ---------------- tf32 flash attention (batched over z), LDSM frags ----------------
// smem words: Q[128][68], K[64][68], V[64][72], P[128][68]
#define QOFF 0
#define KOFF (128*68)
#define VOFF (KOFF + 64*68)
#define POFF (VOFF + 64*72)
#define FLASH_SMEM_U32 (POFF + 128*68)

__global__ __launch_bounds__(256, 2) void flash_tf32(
    const float* __restrict__ Q, const float* __restrict__ K,
    const float* __restrict__ V, float* __restrict__ O)
{
    extern __shared__ uint32_t smu[];
    uint32_t* Vs = smu + VOFF;
    float*    Ps = (float*)(smu + POFF);

    const int z  = blockIdx.z;
    const int bh = blockIdx.y;
    const int b  = bh >> 3;
    const int h  = bh & 7;
    const size_t zo = (size_t)z * ROWS * HIDD;
    const float* Qg = Q + zo + (size_t)bh * Nn * HD;
    const float* Kg = K + zo + (size_t)bh * Nn * HD;
    const float* Vg = V + zo + (size_t)bh * Nn * HD;
    float* Og = O + zo;

    const int t    = threadIdx.x;
    const int lane = t & 31;
    const int warp = t >> 5;
    const int gid  = lane >> 2;
    const int tig  = lane & 3;
    const int q0r  = blockIdx.x * 128;

    const uint32_t qsa = s2u(smu + QOFF);
    const uint32_t ksa = s2u(smu + KOFF);
    const uint32_t vsa = s2u(Vs);
    const uint32_t psa = s2u(Ps);

    // ldsm address components
    const int a_r = ((lane >> 3) & 1)*8 + (lane & 7);
    const int a_c = (lane >> 4) * 4;
    const int b_r = (lane >> 4)*8 + (lane & 7);
    const int b_c = ((lane >> 3) & 1) * 4;

    // stage Q tile [row][68] via cp.async
    #pragma unroll
    for (int i = 0; i < 8; ++i) {
        int idx = t + 256*i;
        int row = idx >> 4, dq = (idx & 15) << 2;
        cpa16(qsa + (uint32_t)(row*68 + dq)*4, Qg + (size_t)(q0r + row)*HD + dq);
    }
    cpa_commit();
    cpa_wait<0>();
    __syncthreads();

    // hoist Q fragments (persist across kv loop)
    uint32_t qf[8][4];
    #pragma unroll
    for (int ks = 0; ks < 8; ++ks)
        ldsm_x4(qf[ks][0], qf[ks][1], qf[ks][2], qf[ks][3],
            qsa + (uint32_t)((warp*16 + a_r)*68 + ks*8 + a_c)*4);

    float accO[8][4] = {};
    float mrow[2] = {-1e30f, -1e30f};
    float lrow[2] = {0.f, 0.f};

    for (int j0 = 0; j0 < Nn; j0 += 64) {
        __syncthreads();   // prior-iter reads of Ks/Vs/Ps complete
        #pragma unroll
        for (int i = 0; i < 4; ++i) {
            int idx = t + 256*i;
            int row = idx >> 4, dq = (idx & 15) << 2;
            cpa16(ksa + (uint32_t)(row*68 + dq)*4, Kg + (size_t)(j0 + row)*HD + dq);
            cpa16(vsa + (uint32_t)(row*72 + dq)*4, Vg + (size_t)(j0 + row)*HD + dq);
        }
        cpa_commit();
        cpa_wait<0>();
        __syncthreads();

        // S = Q @ K^T  (K natural [kv][d] layout == B^T [n][k])
        float s[8][4] = {};
        #pragma unroll
        for (int ks = 0; ks < 8; ++ks) {
            #pragma unroll
            for (int j = 0; j < 4; ++j) {
                uint32_t kf0, kf1, kf2, kf3;
                ldsm_x4(kf0, kf1, kf2, kf3,
                    ksa + (uint32_t)((j*16 + b_r)*68 + ks*8 + b_c)*4);
                mma_tf32(s[2*j],   qf[ks][0], qf[ks][1], qf[ks][2], qf[ks][3], kf0, kf1);
                mma_tf32(s[2*j+1], qf[ks][0], qf[ks][1], qf[ks][2], qf[ks][3], kf2, kf3);
            }
        }

        // online softmax per row-group
        #pragma unroll
        for (int g = 0; g < 2; ++g) {
            float tm = -1e30f;
            #pragma unroll
            for (int nt = 0; nt < 8; ++nt)
                tm = fmaxf(tm, fmaxf(s[nt][2*g], s[nt][2*g+1]));
            tm = fmaxf(tm, __shfl_xor_sync(0xffffffffu, tm, 1));
            tm = fmaxf(tm, __shfl_xor_sync(0xffffffffu, tm, 2));
            float mn = fmaxf(mrow[g], tm);
            float alpha = __expf(mrow[g] - mn);
            mrow[g] = mn;
            float rs = 0.f;
            #pragma unroll
            for (int nt = 0; nt < 8; ++nt) {
                float p0 = __expf(s[nt][2*g]   - mn);
                float p1 = __expf(s[nt][2*g+1] - mn);
                s[nt][2*g] = p0; s[nt][2*g+1] = p1;
                rs += p0 + p1;
            }
            rs += __shfl_xor_sync(0xffffffffu, rs, 1);
            rs += __shfl_xor_sync(0xffffffffu, rs, 2);
            lrow[g] = lrow[g]*alpha + rs;
            #pragma unroll
            for (int nt = 0; nt < 8; ++nt) {
                accO[nt][2*g]   *= alpha;
                accO[nt][2*g+1] *= alpha;
            }
        }

        // store P (raw fp32) to per-warp smem rows
        {
            int r0 = warp*16 + gid;
            #pragma unroll
            for (int nt = 0; nt < 8; ++nt) {
                int pc = nt*8 + 2*tig;
                *(float2*)&Ps[r0*68 + pc]     = make_float2(s[nt][0], s[nt][1]);
                *(float2*)&Ps[(r0+8)*68 + pc] = make_float2(s[nt][2], s[nt][3]);
            }
        }
        __syncwarp();

        // O += P @ V  (P frags via ldsm; V scalar)
        #pragma unroll
        for (int ks = 0; ks < 8; ++ks) {
            uint32_t pf0, pf1, pf2, pf3;
            ldsm_x4(pf0, pf1, pf2, pf3,
                psa + (uint32_t)((warp*16 + a_r)*68 + ks*8 + a_c)*4);
            #pragma unroll
            for (int nt = 0; nt < 8; ++nt) {
                int n = nt*8 + gid;
                int k = ks*8 + tig;
                uint32_t b0 = Vs[k*72 + n];
                uint32_t b1 = Vs[(k+4)*72 + n];
                mma_tf32(accO[nt], pf0, pf1, pf2, pf3, b0, b1);
            }
        }
    }

    #pragma unroll
    for (int g = 0; g < 2; ++g) {
        float inv = 1.0f / lrow[g];
        int n = q0r + warp*16 + gid + 8*g;
        #pragma unroll
        for (int nt = 0; nt < 8; ++nt) {
            int col = h*64 + nt*8 + 2*tig;
            float2 o;
            o.x = accO[nt][2*g]   * inv;
            o.y = accO[nt][2*g+1] * inv;
            *(float2*)&Og[((size_t)b * Nn + n) * HIDD + col] = o;
        }
    }
}

// ---------------- LayerNorm + exact GELU (batched over z) ----------------
__global__ __launch_bounds__(256) void ln_gelu_kernel(
    const float* __restrict__ H, const float* __restrict__ g,
    const float* __restrict__ bta, float* __restrict__ out)
{
    __shared__ float red[256];
    const size_t rowi = (size_t)blockIdx.y * ROWS + blockIdx.x;
    const float* p = H + rowi * (2*FEAT);
    int t = threadIdx.x;
    float4 v = ((const float4*)p)[t];

    float s = v.x + v.y + v.z + v.w;
    red[t] = s; __syncthreads();
    for (int ss = 128; ss > 0; ss >>= 1) {
        if (t < ss) red[t] += red[t+ss];
        __syncthreads();
    }
    float mu = red[0] * (1.0f / (2*FEAT));
    __syncthreads();

    float d0 = v.x - mu, d1 = v.y - mu, d2 = v.z - mu, d3 = v.w - mu;
    red[t] = d0*d0 + d1*d1 + d2*d2 + d3*d3; __syncthreads();
    for (int ss = 128; ss > 0; ss >>= 1) {
        if (t < ss) red[t] += red[t+ss];
        __syncthreads();
    }
    float var = red[0] * (1.0f / (2*FEAT));
    float rs = rsqrtf(var + 1e-5f);

    int c = t << 2;
    float4 gv = *(const float4*)(g + c);
    float4 bv = *(const float4*)(bta + c);
    float y0 = d0 * rs * gv.x + bv.x;
    float y1 = d1 * rs * gv.y + bv.y;
    float y2 = d2 * rs * gv.z + bv.z;
    float y3 = d3 * rs * gv.w + bv.w;

    const float IS2 = 0.70710678118654752f;
    float4 o;
    o.x = 0.5f * y0 * (1.0f + erff(y0 * IS2));
    o.y = 0.5f * y1 * (1.0f + erff(y1 * IS2));
    o.z = 0.5f * y2 * (1.0f + erff(y2 * IS2));
    o.w = 0.5f * y3 * (1.0f + erff(y3 * IS2));
    ((float4*)(out + rowi * (2*FEAT)))[t] = o;
}

extern "C" void kernel_launch(void* const* d_in, const int* in_sizes, int n_in,
                              void* d_out, int out_size)
{
    const float* x0    = (const float*)d_in[0];
    const float* x1    = (const float*)d_in[1];
    const float* enc0  = (const float*)d_in[2];
    const float* enc1  = (const float*)d_in[3];
    const float* Wqkv  = (const float*)d_in[4];
    const float* bqkv  = (const float*)d_in[5];
    const float* Wproj = (const float*)d_in[6];
    const float* bproj = (const float*)d_in[7];
    const float* W1    = (const float*)d_in[8];
    const float* b1    = (const float*)d_in[9];
    const float* ln_g  = (const float*)d_in[10];
    const float* ln_b  = (const float*)d_in[11];
    const float* W2    = (const float*)d_in[12];
    const float* b2    = (const float*)d_in[13];
    float* out = (float*)d_out;

    float *qkv, *q, *k, *v, *o, *msg, *hh, *gg;
    float *wqkvT, *wprojT, *w1T, *w2T;
    cudaGetSymbolAddress((void**)&qkv, g_qkv);
    cudaGetSymbolAddress((void**)&q,   g_q);
    cudaGetSymbolAddress((void**)&k,   g_k);
    cudaGetSymbolAddress((void**)&v,   g_v);
    cudaGetSymbolAddress((void**)&o,   g_o);
    cudaGetSymbolAddress((void**)&msg, g_msg);
    cudaGetSymbolAddress((void**)&hh,  g_h);
    cudaGetSymbolAddress((void**)&gg,  g_g);
    cudaGetSymbolAddress((void**)&wqkvT,  g_wqkvT);
    cudaGetSymbolAddress((void**)&wprojT, g_wprojT);
    cudaGetSymbolAddress((void**)&w1T,    g_w1T);
    cudaGetSymbolAddress((void**)&w2T,    g_w2T);

    cudaFuncSetAttribute(gemm_tf32,
        cudaFuncAttributeMaxDynamicSharedMemorySize, GSM_BYTES);
    cudaFuncSetAttribute(flash_tf32,
        cudaFuncAttributeMaxDynamicSharedMemorySize, FLASH_SMEM_U32*4);

    // transpose weights once per launch (reused by all tiles)
    tr_kernel<<<dim3((3*HIDD)/32, FEAT/32), 256>>>(Wqkv, wqkvT, FEAT, 3*HIDD);
    tr_kernel<<<dim3(HIDD/32, HIDD/32), 256>>>(Wproj, wprojT, HIDD, HIDD);
    tr_kernel<<<dim3((2*FEAT)/32, (FEAT+HIDD)/32), 256>>>(W1, w1T, FEAT+HIDD, 2*FEAT);
    tr_kernel<<<dim3(FEAT/32, (2*FEAT)/32), 256>>>(W2, w2T, 2*FEAT, FEAT);

    const size_t ZQKV = (size_t)ROWS*3*HIDD;
    const size_t ZH   = (size_t)ROWS*HIDD;
    const size_t Z2F  = (size_t)ROWS*2*FEAT;

    // qkv = x @ Wqkv + bqkv
    gemm_tf32<<<dim3(3*HIDD/128, ROWS/128, 2), 256, GSM_BYTES>>>(
        x0, x1, FEAT, nullptr, nullptr, 0, 1<<30,
        wqkvT, bqkv, nullptr, nullptr, 0,
        qkv, ZQKV, 3*HIDD, FEAT);

    rope_kernel<<<dim3((Bb*Nn*Hh*(HD/2))/256, 2), 256>>>(qkv, enc0, enc1, q, k, v);

    flash_tf32<<<dim3(Nn/128, BH, 2), 256, FLASH_SMEM_U32*4>>>(q, k, v, o);

    // message = O @ Wproj + bproj
    gemm_tf32<<<dim3(HIDD/128, ROWS/128, 2), 256, GSM_BYTES>>>(
        o, o + ZH, HIDD, nullptr, nullptr, 0, 1<<30,
        wprojT, bproj, nullptr, nullptr, 0,
        msg, ZH, HIDD, HIDD);

    // h = concat(x, msg) @ W1 + b1
    gemm_tf32<<<dim3(2*FEAT/128, ROWS/128, 2), 256, GSM_BYTES>>>(
        x0, x1, FEAT, msg, msg + ZH, HIDD, FEAT,
        w1T, b1, nullptr, nullptr, 0,
        hh, Z2F, 2*FEAT, FEAT + HIDD);

    ln_gelu_kernel<<<dim3(ROWS, 2), 256>>>(hh, ln_g, ln_b, gg);

    // out = x + g @ W2 + b2
    gemm_tf32<<<dim3(FEAT/128, ROWS/128, 2), 256, GSM_BYTES>>>(
        gg, gg + Z2F, 2*FEAT, nullptr, nullptr, 0, 1<<30,
        w2T, b2, x0, x1, FEAT,
        out, (size_t)ROWS*FEAT, FEAT, 2*FEAT);
}